// round 1
// baseline (speedup 1.0000x reference)
#include <cuda_runtime.h>

#define BATCH 16
#define HW    16384
#define C     64

// k1: 64 chunks per batch, 256 rows per chunk, 32-row smem tiles
#define K1_CHUNKS 64
#define K1_ROWS   256

// Deterministic scratch (no atomics, fully overwritten every launch)
__device__ float g_partial[BATCH * K1_CHUNKS * C * C];  // 16 MB
__device__ float g_attn[BATCH * C * C];

__device__ __forceinline__ void ffma2(unsigned long long &d,
                                      unsigned long long a,
                                      unsigned long long b) {
    asm("fma.rn.f32x2 %0, %1, %2, %0;" : "+l"(d) : "l"(a), "l"(b));
}

// ---------------------------------------------------------------------------
// Kernel 1: partial scores.  S_partial[b][chunk][q][k] = sum_{rows in chunk}
//           Q[b][row][q] * K[b][row][k]
// 128 threads: tx = k-group (8 k each), ty = q-group (4 q each).
// Q stored DUPLICATED in smem so f32x2 needs no MOV packing.
// ---------------------------------------------------------------------------
__global__ __launch_bounds__(128) void k1_scores(const float* __restrict__ Q,
                                                 const float* __restrict__ K) {
    __shared__ __align__(16) float Qd[32][132];  // duplicated: Qd[r][2q],Qd[r][2q+1]
    __shared__ __align__(16) float Ks[32][68];

    int b     = blockIdx.x >> 6;
    int chunk = blockIdx.x & 63;
    int row0  = chunk * K1_ROWS;
    int t  = threadIdx.x;
    int tx = t & 7;    // 0..7   -> k = 8*tx .. 8*tx+7 (4 f32x2 pairs)
    int ty = t >> 3;   // 0..15  -> q = 4*ty .. 4*ty+3

    unsigned long long c2[4][4];
#pragma unroll
    for (int i = 0; i < 4; ++i)
#pragma unroll
        for (int j = 0; j < 4; ++j) c2[i][j] = 0ull;  // bits of (0.f,0.f)

    const float* Qb = Q + ((size_t)b * HW + row0) * C;
    const float* Kb = K + ((size_t)b * HW + row0) * C;

    for (int tile = 0; tile < 8; ++tile) {
        // stage 32 rows of Q (duplicated) and K
#pragma unroll
        for (int it = 0; it < 4; ++it) {
            int idx = t + it * 128;          // 0..511
            int r = idx >> 4, c4 = idx & 15;
            const float* qp = Qb + (size_t)(tile * 32 + r) * C + c4 * 4;
            const float* kp = Kb + (size_t)(tile * 32 + r) * C + c4 * 4;
            float4 q4 = *(const float4*)qp;
            float4 k4 = *(const float4*)kp;
            float* qd = &Qd[r][c4 * 8];
            *(float4*)(qd)     = make_float4(q4.x, q4.x, q4.y, q4.y);
            *(float4*)(qd + 4) = make_float4(q4.z, q4.z, q4.w, q4.w);
            *(float4*)(&Ks[r][c4 * 4]) = k4;
        }
        __syncthreads();

#pragma unroll 8
        for (int r = 0; r < 32; ++r) {
            ulonglong2 qa = *(const ulonglong2*)&Qd[r][ty * 8];
            ulonglong2 qb = *(const ulonglong2*)&Qd[r][ty * 8 + 4];
            ulonglong2 ka = *(const ulonglong2*)&Ks[r][tx * 8];
            ulonglong2 kb = *(const ulonglong2*)&Ks[r][tx * 8 + 4];
            unsigned long long qq[4] = {qa.x, qa.y, qb.x, qb.y};
            unsigned long long kp[4] = {ka.x, ka.y, kb.x, kb.y};
#pragma unroll
            for (int i = 0; i < 4; ++i)
#pragma unroll
                for (int j = 0; j < 4; ++j) ffma2(c2[i][j], qq[i], kp[j]);
        }
        __syncthreads();
    }

    float* pb = g_partial + (size_t)(b * K1_CHUNKS + chunk) * (C * C);
#pragma unroll
    for (int i = 0; i < 4; ++i) {
        int q = ty * 4 + i;
        *(ulonglong2*)(pb + q * C + tx * 8)     = make_ulonglong2(c2[i][0], c2[i][1]);
        *(ulonglong2*)(pb + q * C + tx * 8 + 4) = make_ulonglong2(c2[i][2], c2[i][3]);
    }
}

// ---------------------------------------------------------------------------
// Kernel 2: reduce 64 chunk partials + softmax over k.
// 256 blocks (16 batches x 16 q-groups of 4 rows), 256 threads.
// ---------------------------------------------------------------------------
__global__ __launch_bounds__(256) void k2_softmax() {
    __shared__ float S[256];
    int b  = blockIdx.x >> 4;
    int qg = blockIdx.x & 15;     // 4 q-rows per block
    int t  = threadIdx.x;
    int q  = qg * 4 + (t >> 6);   // local rows 0..3
    int k  = t & 63;

    const float* p = g_partial + (size_t)b * K1_CHUNKS * (C * C) + q * C + k;
    float acc = 0.f;
#pragma unroll 8
    for (int ch = 0; ch < K1_CHUNKS; ++ch) acc += p[(size_t)ch * (C * C)];
    S[t] = acc;
    __syncthreads();

    int w = t >> 5, lane = t & 31;
    if (w < 4) {
        float e0 = S[w * 64 + lane];
        float e1 = S[w * 64 + 32 + lane];
        float m = fmaxf(e0, e1);
#pragma unroll
        for (int o = 16; o > 0; o >>= 1) m = fmaxf(m, __shfl_xor_sync(~0u, m, o));
        float x0 = expf(e0 - m), x1 = expf(e1 - m);
        float s = x0 + x1;
#pragma unroll
        for (int o = 16; o > 0; o >>= 1) s += __shfl_xor_sync(~0u, s, o);
        float inv = 1.f / s;
        float* a = g_attn + (size_t)b * (C * C) + (qg * 4 + w) * C;
        a[lane]      = x0 * inv;
        a[lane + 32] = x1 * inv;
    }
}

// ---------------------------------------------------------------------------
// Kernel 3: out[b][row][q] = sum_k attn[b][q][k] * V[b][row][k]
// A stored transposed (At[k][q]) once per block; V stored DUPLICATED per
// 32-row subtile so the f32x2 inner loop has zero MOVs.
// 128 threads: tx = q-group (4 q = 2 pairs), ty = row-group (4 rows).
// ---------------------------------------------------------------------------
__global__ __launch_bounds__(128) void k3_out(const float* __restrict__ V,
                                              float* __restrict__ O) {
    __shared__ __align__(16) float At[64][68];   // At[k][q] = attn[q][k]
    __shared__ __align__(16) float Vd[64][68];   // Vd[k][2r],[2r+1] = dup V[row r][k]

    int b    = blockIdx.x >> 6;
    int rc   = blockIdx.x & 63;
    int row0 = rc * 256;
    int t  = threadIdx.x;
    int tx = t & 15;   // q = 4*tx .. 4*tx+3
    int ty = t >> 4;   // rows = 4*ty .. 4*ty+3 (0..7 -> 32 rows/subtile)

    const float* ab = g_attn + (size_t)b * (C * C);
#pragma unroll
    for (int it = 0; it < 32; ++it) {
        int idx = t + it * 128;        // 0..4095
        int q = idx >> 6, k = idx & 63;
        At[k][q] = ab[idx];
    }

    const float* Vb = V + ((size_t)b * HW + row0) * C;
    float*       Ob = O + ((size_t)b * HW + row0) * C;

    for (int st = 0; st < 8; ++st) {
        __syncthreads();   // At ready (st=0) / Vd reuse safe (st>0)
#pragma unroll
        for (int it = 0; it < 4; ++it) {
            int idx = t + it * 128;    // 0..511 : 32 rows x 16 float4
            int r = idx >> 4, k4 = idx & 15;
            float4 v4 = *(const float4*)(Vb + (size_t)(st * 32 + r) * C + k4 * 4);
            *(float2*)&Vd[k4 * 4 + 0][2 * r] = make_float2(v4.x, v4.x);
            *(float2*)&Vd[k4 * 4 + 1][2 * r] = make_float2(v4.y, v4.y);
            *(float2*)&Vd[k4 * 4 + 2][2 * r] = make_float2(v4.z, v4.z);
            *(float2*)&Vd[k4 * 4 + 3][2 * r] = make_float2(v4.w, v4.w);
        }
        __syncthreads();

        unsigned long long c2[4][2];
#pragma unroll
        for (int i = 0; i < 4; ++i) { c2[i][0] = 0ull; c2[i][1] = 0ull; }

#pragma unroll 8
        for (int k = 0; k < 64; ++k) {
            ulonglong2 va  = *(const ulonglong2*)&Vd[k][ty * 8];
            ulonglong2 vb2 = *(const ulonglong2*)&Vd[k][ty * 8 + 4];
            ulonglong2 aa  = *(const ulonglong2*)&At[k][tx * 4];
            unsigned long long vv[4] = {va.x, va.y, vb2.x, vb2.y};
#pragma unroll
            for (int i = 0; i < 4; ++i) {
                ffma2(c2[i][0], vv[i], aa.x);
                ffma2(c2[i][1], vv[i], aa.y);
            }
        }
#pragma unroll
        for (int i = 0; i < 4; ++i) {
            int row = st * 32 + ty * 4 + i;
            *(ulonglong2*)(Ob + (size_t)row * C + tx * 4) =
                make_ulonglong2(c2[i][0], c2[i][1]);
        }
    }
}

// ---------------------------------------------------------------------------
extern "C" void kernel_launch(void* const* d_in, const int* in_sizes, int n_in,
                              void* d_out, int out_size) {
    const float* q = (const float*)d_in[0];
    const float* k = (const float*)d_in[1];
    const float* v = (const float*)d_in[2];
    float* out = (float*)d_out;

    k1_scores<<<BATCH * K1_CHUNKS, 128>>>(q, k);
    k2_softmax<<<BATCH * 16, 256>>>();
    k3_out<<<BATCH * 64, 128>>>(v, out);
}

// round 2
// speedup vs baseline: 1.5830x; 1.5830x over previous
#include <cuda_runtime.h>

#define BATCH 16
#define HW    16384
#define C     64
#define K1_CHUNKS 64

// Deterministic scratch (no atomics, fully overwritten every launch)
__device__ float g_partial[BATCH * K1_CHUNKS * C * C];  // 16 MB
__device__ float g_attn[BATCH * C * C];

__device__ __forceinline__ void ffma2(unsigned long long &d,
                                      unsigned long long a,
                                      unsigned long long b) {
    asm("fma.rn.f32x2 %0, %1, %2, %0;" : "+l"(d) : "l"(a), "l"(b));
}

// duplicate a float into both halves of an f32x2 register pair (1 MOV, alu pipe)
__device__ __forceinline__ unsigned long long dup2(float v) {
    unsigned long long d;
    asm("mov.b64 %0, {%1, %1};" : "=l"(d) : "f"(v));
    return d;
}

// ---------------------------------------------------------------------------
// Kernel 1: partial scores.  S_partial[b][chunk][q][k] = sum_rows Q[r][q]*K[r][k]
// 64 threads: tx = k-group (8 k = 4 pairs), ty = q-group (8 q, reg-duplicated).
// Thread tile 8q x 8k -> 32 FFMA2 per row vs 4 LDS.128 + 8 MOV.
// ---------------------------------------------------------------------------
__global__ __launch_bounds__(64) void k1_scores(const float* __restrict__ Q,
                                                const float* __restrict__ K) {
    __shared__ __align__(16) float Qs[32][68];
    __shared__ __align__(16) float Ks[32][68];

    int b     = blockIdx.x >> 6;
    int chunk = blockIdx.x & 63;
    int t  = threadIdx.x;
    int tx = t & 7;    // k = 8*tx .. 8*tx+7
    int ty = t >> 3;   // q = 8*ty .. 8*ty+7

    unsigned long long c2[8][4];
#pragma unroll
    for (int i = 0; i < 8; ++i)
#pragma unroll
        for (int j = 0; j < 4; ++j) c2[i][j] = 0ull;

    const float* Qb = Q + ((size_t)b * HW + chunk * 256) * C;
    const float* Kb = K + ((size_t)b * HW + chunk * 256) * C;

    for (int tile = 0; tile < 8; ++tile) {
        // stage 32 rows of Q and K (coalesced float4)
#pragma unroll
        for (int it = 0; it < 8; ++it) {
            int idx = t + it * 64;           // 0..511
            int r = idx >> 4, c4 = idx & 15;
            const float* src = Qb + (size_t)(tile * 32 + r) * C + c4 * 4;
            *(float4*)&Qs[r][c4 * 4] = *(const float4*)src;
            src = Kb + (size_t)(tile * 32 + r) * C + c4 * 4;
            *(float4*)&Ks[r][c4 * 4] = *(const float4*)src;
        }
        __syncthreads();

#pragma unroll 4
        for (int r = 0; r < 32; ++r) {
            float4 qa = *(const float4*)&Qs[r][ty * 8];
            float4 qb = *(const float4*)&Qs[r][ty * 8 + 4];
            ulonglong2 ka = *(const ulonglong2*)&Ks[r][tx * 8];
            ulonglong2 kb = *(const ulonglong2*)&Ks[r][tx * 8 + 4];
            unsigned long long kk[4] = {ka.x, ka.y, kb.x, kb.y};
            unsigned long long qd[8] = {dup2(qa.x), dup2(qa.y), dup2(qa.z), dup2(qa.w),
                                        dup2(qb.x), dup2(qb.y), dup2(qb.z), dup2(qb.w)};
#pragma unroll
            for (int i = 0; i < 8; ++i)
#pragma unroll
                for (int j = 0; j < 4; ++j) ffma2(c2[i][j], qd[i], kk[j]);
        }
        __syncthreads();
    }

    float* pb = g_partial + (size_t)(b * K1_CHUNKS + chunk) * (C * C);
#pragma unroll
    for (int i = 0; i < 8; ++i) {
        int q = ty * 8 + i;
        *(ulonglong2*)(pb + q * C + tx * 8)     = make_ulonglong2(c2[i][0], c2[i][1]);
        *(ulonglong2*)(pb + q * C + tx * 8 + 4) = make_ulonglong2(c2[i][2], c2[i][3]);
    }
}

// ---------------------------------------------------------------------------
// Kernel 2: reduce 64 chunk partials + softmax over k (unchanged, ~8us)
// ---------------------------------------------------------------------------
__global__ __launch_bounds__(256) void k2_softmax() {
    __shared__ float S[256];
    int b  = blockIdx.x >> 4;
    int qg = blockIdx.x & 15;
    int t  = threadIdx.x;
    int q  = qg * 4 + (t >> 6);
    int k  = t & 63;

    const float* p = g_partial + (size_t)b * K1_CHUNKS * (C * C) + q * C + k;
    float acc = 0.f;
#pragma unroll 8
    for (int ch = 0; ch < K1_CHUNKS; ++ch) acc += p[(size_t)ch * (C * C)];
    S[t] = acc;
    __syncthreads();

    int w = t >> 5, lane = t & 31;
    if (w < 4) {
        float e0 = S[w * 64 + lane];
        float e1 = S[w * 64 + 32 + lane];
        float m = fmaxf(e0, e1);
#pragma unroll
        for (int o = 16; o > 0; o >>= 1) m = fmaxf(m, __shfl_xor_sync(~0u, m, o));
        float x0 = expf(e0 - m), x1 = expf(e1 - m);
        float s = x0 + x1;
#pragma unroll
        for (int o = 16; o > 0; o >>= 1) s += __shfl_xor_sync(~0u, s, o);
        float inv = 1.f / s;
        float* a = g_attn + (size_t)b * (C * C) + (qg * 4 + w) * C;
        a[lane]      = x0 * inv;
        a[lane + 32] = x1 * inv;
    }
}

// ---------------------------------------------------------------------------
// Kernel 3: out[b][row][q] = sum_k attn[b][q][k] * V[b][row][k]
// 64 threads: tx = q-group (8 q = 4 pairs from At), ty = row-group (8 rows).
// V read as float4 along k (4 k per step, conflict-free), reg-duplicated.
// ---------------------------------------------------------------------------
__global__ __launch_bounds__(64) void k3_out(const float* __restrict__ V,
                                             float* __restrict__ O) {
    __shared__ __align__(16) float At[64][68];   // At[k][q] = attn[q][k]
    __shared__ __align__(16) float Vs[64][68];   // Vs[row][k]

    int b  = blockIdx.x >> 6;
    int rc = blockIdx.x & 63;
    int t  = threadIdx.x;
    int tx = t & 7;    // q = 8*tx .. 8*tx+7
    int ty = t >> 3;   // rows = 8*ty .. 8*ty+7 within 64-row stage

    const float* ab = g_attn + (size_t)b * (C * C);
#pragma unroll
    for (int it = 0; it < 64; ++it) {
        int idx = t + it * 64;       // 0..4095
        int q = idx >> 6, k = idx & 63;
        At[k][q] = ab[idx];
    }

    const float* Vb = V + ((size_t)b * HW + rc * 256) * C;
    float*       Ob = O + ((size_t)b * HW + rc * 256) * C;

    for (int st = 0; st < 4; ++st) {
        __syncthreads();   // At ready (st=0) / Vs reuse safe (st>0)
#pragma unroll
        for (int it = 0; it < 16; ++it) {
            int idx = t + it * 64;   // 0..1023 : 64 rows x 16 float4
            int r = idx >> 4, c4 = idx & 15;
            *(float4*)&Vs[r][c4 * 4] =
                *(const float4*)(Vb + (size_t)(st * 64 + r) * C + c4 * 4);
        }
        __syncthreads();

        unsigned long long c2[8][4];  // [row][q-pair]
#pragma unroll
        for (int i = 0; i < 8; ++i)
#pragma unroll
            for (int j = 0; j < 4; ++j) c2[i][j] = 0ull;

#pragma unroll 2
        for (int k4 = 0; k4 < 16; ++k4) {
            int k0 = k4 * 4;
            float4 vv[8];
#pragma unroll
            for (int i = 0; i < 8; ++i)
                vv[i] = *(const float4*)&Vs[ty * 8 + i][k0];
#pragma unroll
            for (int kk = 0; kk < 4; ++kk) {
                int k = k0 + kk;
                ulonglong2 a0 = *(const ulonglong2*)&At[k][tx * 8];
                ulonglong2 a1 = *(const ulonglong2*)&At[k][tx * 8 + 4];
                unsigned long long aa[4] = {a0.x, a0.y, a1.x, a1.y};
#pragma unroll
                for (int i = 0; i < 8; ++i) {
                    float v = (kk == 0) ? vv[i].x : (kk == 1) ? vv[i].y
                            : (kk == 2) ? vv[i].z : vv[i].w;
                    unsigned long long vd = dup2(v);
                    ffma2(c2[i][0], vd, aa[0]);
                    ffma2(c2[i][1], vd, aa[1]);
                    ffma2(c2[i][2], vd, aa[2]);
                    ffma2(c2[i][3], vd, aa[3]);
                }
            }
        }

#pragma unroll
        for (int i = 0; i < 8; ++i) {
            int row = st * 64 + ty * 8 + i;
            *(ulonglong2*)(Ob + (size_t)row * C + tx * 8) =
                make_ulonglong2(c2[i][0], c2[i][1]);
            *(ulonglong2*)(Ob + (size_t)row * C + tx * 8 + 4) =
                make_ulonglong2(c2[i][2], c2[i][3]);
        }
    }
}

// ---------------------------------------------------------------------------
extern "C" void kernel_launch(void* const* d_in, const int* in_sizes, int n_in,
                              void* d_out, int out_size) {
    const float* q = (const float*)d_in[0];
    const float* k = (const float*)d_in[1];
    const float* v = (const float*)d_in[2];
    float* out = (float*)d_out;

    k1_scores<<<BATCH * K1_CHUNKS, 64>>>(q, k);
    k2_softmax<<<BATCH * 16, 256>>>();
    k3_out<<<BATCH * K1_CHUNKS, 64>>>(v, out);
}